// round 6
// baseline (speedup 1.0000x reference)
#include <cuda_runtime.h>

#define TT 1024
#define BB 512
#define DD 128
#define NO 11                 // 0=f,1=i,2=o,3..10=g0..g7
#define PSTR (NO*BB)
#define PREPB 128             // prep blocks; each rep covers 2 consecutive t
#define REPS 4
#define RECB 16               // recur blocks: warp0 active, 32 batch each

__device__ float g_pre[TT * NO * BB];     // ~23 MB scratch, [t][k][B]
__device__ unsigned g_ready[TT];          // zero-init at load; monotonic flags

typedef unsigned long long u64;

__device__ __forceinline__ u64 pack2(float lo, float hi){
    u64 r; asm("mov.b64 %0, {%1, %2};" : "=l"(r) : "f"(lo), "f"(hi)); return r;
}
__device__ __forceinline__ void unpack2(u64 v, float& lo, float& hi){
    asm("mov.b64 {%0, %1}, %2;" : "=f"(lo), "=f"(hi) : "l"(v));
}
__device__ __forceinline__ u64 fma2(u64 a, u64 b, u64 c){
    u64 d; asm("fma.rn.f32x2 %0, %1, %2, %3;" : "=l"(d) : "l"(a), "l"(b), "l"(c));
    return d;
}
__device__ __forceinline__ u64 mul2(u64 a, u64 b){
    u64 d; asm("mul.rn.f32x2 %0, %1, %2;" : "=l"(d) : "l"(a), "l"(b));
    return d;
}

__device__ __forceinline__ float f4c(const float4 v, int kk){
    return kk==0 ? v.x : kk==1 ? v.y : kk==2 ? v.z : v.w;
}

__device__ __forceinline__ float tanh_fast(float v){
    return 1.0f - __fdividef(2.0f, __expf(2.0f*v) + 1.0f);
}

// sigmoid(u), u in [-1,1]: 0.5 + u*P(u^2), Estrin, |err| ~ 2e-7
__device__ __forceinline__ float sigm_poly(float u){
    const float t  = u*u;
    const float E0 = fmaf(t, -2.0833334e-2f, 0.25f);
    const float E1 = fmaf(t, -2.10821e-4f,   2.0833334e-3f);
    const float E2 = fmaf(t, -2.16387e-6f,   2.13570e-5f);
    const float t2 = t*t;
    const float P  = fmaf(t2, fmaf(t2, E2, E1), E0);
    return fmaf(u, P, 0.5f);
}

__global__ void __launch_bounds__(256) fused_kernel(
    const float* __restrict__ x,
    const float* __restrict__ Wf, const float* __restrict__ bf,
    const float* __restrict__ Wi, const float* __restrict__ bi,
    const float* __restrict__ Wu, const float* __restrict__ bu,
    const float* __restrict__ Wo, const float* __restrict__ bo,
    const float* __restrict__ qwf, const float* __restrict__ qwi,
    const float* __restrict__ qwo,
    float* __restrict__ out, int write_tail)
{
    const int bid = blockIdx.x;
    const int tid = threadIdx.x;

    if (bid < PREPB){
        // ================= PREP ROLE =================
        __shared__ __align__(16) float wsm[DD*12];
        __shared__ float bsm[12];
        {
            if (tid < DD){
                const int k = tid;
                wsm[k*12+0] = Wf[k];
                wsm[k*12+1] = Wi[k];
                wsm[k*12+2] = Wo[k];
#pragma unroll
                for (int u = 0; u < 8; u++) wsm[k*12+3+u] = Wu[u*136 + k];
                wsm[k*12+11] = 0.0f;
            }
            if (tid == 0){
                bsm[0] = bf[0]; bsm[1] = bi[0]; bsm[2] = bo[0];
                for (int u = 0; u < 8; u++) bsm[3+u] = bu[u];
                bsm[11] = 0.0f;
            }
        }
        __syncthreads();

        const int half = tid >> 7;
        const int lt   = tid & 127;

        for (int rep = 0; rep < REPS; rep++){
            const int t0 = 2*(bid + rep*PREPB);   // low t finish first
            const int t  = t0 + half;
            const float4* __restrict__ xp =
                (const float4*)x + ((long long)t*BB + lt*4)*(DD/4);

            float acc[4][NO];
#pragma unroll
            for (int r = 0; r < 4; r++)
#pragma unroll
                for (int j = 0; j < NO; j++) acc[r][j] = bsm[j];

#pragma unroll 2
            for (int c = 0; c < 32; c++){
                float4 xv[4];
#pragma unroll
                for (int r = 0; r < 4; r++) xv[r] = xp[r*32 + c];
#pragma unroll
                for (int kk = 0; kk < 4; kk++){
                    const int k = c*4 + kk;
                    const float4* wr = (const float4*)&wsm[k*12];
                    const float4 wa = wr[0], wb = wr[1], wc = wr[2];
                    const float w[NO] = {wa.x,wa.y,wa.z,wa.w,
                                         wb.x,wb.y,wb.z,wb.w,
                                         wc.x,wc.y,wc.z};
#pragma unroll
                    for (int r = 0; r < 4; r++){
                        const float xs = f4c(xv[r], kk);
#pragma unroll
                        for (int j = 0; j < NO; j++)
                            acc[r][j] = fmaf(xs, w[j], acc[r][j]);
                    }
                }
            }

            float* op = g_pre + (long long)t*PSTR + lt*4;
#pragma unroll
            for (int j = 0; j < NO; j++)
                *(float4*)(op + j*BB) =
                    make_float4(acc[0][j],acc[1][j],acc[2][j],acc[3][j]);

            __threadfence();
            __syncthreads();
            if (tid == 0){
                asm volatile("st.release.gpu.global.b32 [%0], %1;"
                             :: "l"(&g_ready[t0]),   "r"(1u) : "memory");
                asm volatile("st.release.gpu.global.b32 [%0], %1;"
                             :: "l"(&g_ready[t0+1]), "r"(1u) : "memory");
            }
        }
        return;
    }

    // ================= RECUR ROLE =================
    // 16 blocks; only warp 0 works (other warps exit -> free issue slots).
    // 1 thread per batch element: the whole recurrence lives in registers.
    if (tid >= 32) return;
    const int lane = tid;
    const int b    = (bid - PREPB)*32 + lane;

    // Packed weights: W2[j][p] = (w_{j,2p}, w_{j,2p+1}) over hidden index
    u64 W2[NO][4];
#pragma unroll
    for (int p = 0; p < 4; p++){
        W2[0][p] = pack2(Wf[DD + 2*p], Wf[DD + 2*p + 1]);
        W2[1][p] = pack2(Wi[DD + 2*p], Wi[DD + 2*p + 1]);
        W2[2][p] = pack2(Wo[DD + 2*p], Wo[DD + 2*p + 1]);
#pragma unroll
        for (int u = 0; u < 8; u++)
            W2[3+u][p] = pack2(Wu[u*136 + DD + 2*p], Wu[u*136 + DD + 2*p + 1]);
    }
    const float cgf = cosf(qwf[0]);
    const float cgi = cosf(qwi[0]);
    const float cgo = cosf(qwo[0]);

    u64 H2[4], C2[4];
#pragma unroll
    for (int p = 0; p < 4; p++){ H2[p] = pack2(0.f,0.f); C2[p] = pack2(0.f,0.f); }

    const float* __restrict__ pre = g_pre + b;
    float pr[4][NO];

    const unsigned m = 0xffffffffu;

    auto POLL = [&](int tbase){
        int tp = tbase + (lane & 3);
        if (tp > TT-1) tp = TT-1;
        const unsigned* fp = &g_ready[tp];
        unsigned v;
        do {
            asm volatile("ld.acquire.gpu.global.b32 %0, [%1];"
                         : "=r"(v) : "l"(fp) : "memory");
        } while (!__all_sync(m, v != 0));
        asm volatile("fence.acq_rel.gpu;" ::: "memory");
    };

    auto LOAD = [&](float* p, int t){
        const float* base = pre + (long long)t*PSTR;
#pragma unroll
        for (int k = 0; k < NO; k++) p[k] = __ldg(base + k*BB);
    };

    auto STEP = [&](int t, const float* p){
        float z[NO];
#pragma unroll
        for (int j = 0; j < NO; j++){
            u64 acc = pack2(p[j], 0.0f);
            acc = fma2(W2[j][0], H2[0], acc);
            acc = fma2(W2[j][1], H2[1], acc);
            acc = fma2(W2[j][2], H2[2], acc);
            acc = fma2(W2[j][3], H2[3], acc);
            float lo, hi; unpack2(acc, lo, hi);
            z[j] = lo + hi;
        }
        const float f = sigm_poly(cgf * __cosf(z[0]));
        const float i = sigm_poly(cgi * __cosf(z[1]));
        const float o = sigm_poly(cgo * __cosf(z[2]));

        float g[8];
#pragma unroll
        for (int r = 0; r < 8; r++) g[r] = tanh_fast(z[3+r]);

        const u64 F2 = pack2(f, f), I2 = pack2(i, i), O2 = pack2(o, o);
#pragma unroll
        for (int pi = 0; pi < 4; pi++){
            const u64 G2 = pack2(g[2*pi], g[2*pi+1]);
            C2[pi] = fma2(F2, C2[pi], mul2(I2, G2));
            float ca, cb; unpack2(C2[pi], ca, cb);
            H2[pi] = mul2(O2, pack2(tanh_fast(ca), tanh_fast(cb)));
        }

        ulonglong2* op = (ulonglong2*)(out + ((long long)t*BB + b)*8);
        op[0] = make_ulonglong2(H2[0], H2[1]);
        op[1] = make_ulonglong2(H2[2], H2[3]);
    };

    POLL(0);
#pragma unroll
    for (int ph = 0; ph < 4; ph++) LOAD(pr[ph], ph);

    for (int tb = 0; tb < TT; tb += 4){
        POLL(tb + 4);                    // clamped inside; cheap when set
#pragma unroll
        for (int ph = 0; ph < 4; ph++){
            STEP(tb + ph, pr[ph]);
            int tn = tb + ph + 4; if (tn >= TT) tn = TT - 1;
            LOAD(pr[ph], tn);
        }
    }

    if (write_tail){
        float* hp = out + (long long)TT*BB*8;
        ulonglong2* hq = (ulonglong2*)(hp + b*8);
        hq[0] = make_ulonglong2(H2[0], H2[1]);
        hq[1] = make_ulonglong2(H2[2], H2[3]);
        ulonglong2* cq = (ulonglong2*)(hp + BB*8 + b*8);
        cq[0] = make_ulonglong2(C2[0], C2[1]);
        cq[1] = make_ulonglong2(C2[2], C2[3]);
    }
}

// ---------------------------------------------------------------------------
extern "C" void kernel_launch(void* const* d_in, const int* in_sizes, int n_in,
                              void* d_out, int out_size)
{
    const float* x   = (const float*)d_in[0];
    const float* Wf  = (const float*)d_in[1];
    const float* bf  = (const float*)d_in[2];
    const float* Wi  = (const float*)d_in[3];
    const float* bi  = (const float*)d_in[4];
    const float* Wu  = (const float*)d_in[5];
    const float* bu  = (const float*)d_in[6];
    const float* Wo  = (const float*)d_in[7];
    const float* bo  = (const float*)d_in[8];
    const float* qwf = (const float*)d_in[9];
    const float* qwi = (const float*)d_in[10];
    // d_in[11] = qwu: unused — g path has no quantum gate in the reference
    const float* qwo = (const float*)d_in[12];
    float* out = (float*)d_out;

    const int write_tail = (out_size >= TT*BB*8 + 2*BB*8) ? 1 : 0;

    fused_kernel<<<PREPB + RECB, 256>>>(x, Wf, bf, Wi, bi, Wu, bu, Wo, bo,
                                        qwf, qwi, qwo, out, write_tail);
}

// round 7
// speedup vs baseline: 1.3470x; 1.3470x over previous
#include <cuda_runtime.h>

#define TT 1024
#define BB 512
#define DD 128
#define NO 11                 // 0=f,1=i,2=o,3..10=g0..g7
#define PSTR (NO*BB)
#define PREPB 256             // prep blocks (128 thr), REPS timesteps each
#define REPS 4
#define RECB 8                // recur blocks: 128 thr = 4 warps, 64 batch each

__device__ float g_pre[TT * NO * BB];     // ~23 MB scratch, [t][k][B]
__device__ unsigned g_ready[TT];          // zero-init at load; monotonic flags

__device__ __forceinline__ float f4c(const float4 v, int kk){
    return kk==0 ? v.x : kk==1 ? v.y : kk==2 ? v.z : v.w;
}

__device__ __forceinline__ float tanh_fast(float v){
    return 1.0f - __fdividef(2.0f, __expf(2.0f*v) + 1.0f);
}

// sigmoid(u), u in [-1,1]: 0.5 + u*P(u^2), Estrin, |err| ~ 2e-7
__device__ __forceinline__ float sigm_poly(float u){
    const float t  = u*u;
    const float E0 = fmaf(t, -2.0833334e-2f, 0.25f);
    const float E1 = fmaf(t, -2.10821e-4f,   2.0833334e-3f);
    const float E2 = fmaf(t, -2.16387e-6f,   2.13570e-5f);
    const float t2 = t*t;
    const float P  = fmaf(t2, fmaf(t2, E2, E1), E0);
    return fmaf(u, P, 0.5f);
}

__global__ void __launch_bounds__(128) fused_kernel(
    const float* __restrict__ x,
    const float* __restrict__ Wf, const float* __restrict__ bf,
    const float* __restrict__ Wi, const float* __restrict__ bi,
    const float* __restrict__ Wu, const float* __restrict__ bu,
    const float* __restrict__ Wo, const float* __restrict__ bo,
    const float* __restrict__ qwf, const float* __restrict__ qwi,
    const float* __restrict__ qwo,
    float* __restrict__ out, int write_tail)
{
    const int bid = blockIdx.x;
    const int tid = threadIdx.x;

    if (bid < PREPB){
        // ================= PREP ROLE (identical to R4's proven version) ======
        __shared__ __align__(16) float wsm[DD*12];
        __shared__ float bsm[12];
        {
            const int k = tid;
            wsm[k*12+0] = Wf[k];
            wsm[k*12+1] = Wi[k];
            wsm[k*12+2] = Wo[k];
#pragma unroll
            for (int u = 0; u < 8; u++) wsm[k*12+3+u] = Wu[u*136 + k];
            wsm[k*12+11] = 0.0f;
            if (tid == 0){
                bsm[0] = bf[0]; bsm[1] = bi[0]; bsm[2] = bo[0];
                for (int u = 0; u < 8; u++) bsm[3+u] = bu[u];
                bsm[11] = 0.0f;
            }
        }
        __syncthreads();

        for (int rep = 0; rep < REPS; rep++){
            const int t = bid + rep*PREPB;          // low t finish first
            const float4* __restrict__ xp =
                (const float4*)x + ((long long)t*BB + tid*4)*(DD/4);

            float acc[4][NO];
#pragma unroll
            for (int r = 0; r < 4; r++)
#pragma unroll
                for (int j = 0; j < NO; j++) acc[r][j] = bsm[j];

#pragma unroll 2
            for (int c = 0; c < 32; c++){
                float4 xv[4];
#pragma unroll
                for (int r = 0; r < 4; r++) xv[r] = xp[r*32 + c];
#pragma unroll
                for (int kk = 0; kk < 4; kk++){
                    const int k = c*4 + kk;
                    const float4* wr = (const float4*)&wsm[k*12];
                    const float4 wa = wr[0], wb = wr[1], wc = wr[2];
                    const float w[NO] = {wa.x,wa.y,wa.z,wa.w,
                                         wb.x,wb.y,wb.z,wb.w,
                                         wc.x,wc.y,wc.z};
#pragma unroll
                    for (int r = 0; r < 4; r++){
                        const float xs = f4c(xv[r], kk);
#pragma unroll
                        for (int j = 0; j < NO; j++)
                            acc[r][j] = fmaf(xs, w[j], acc[r][j]);
                    }
                }
            }

            float* op = g_pre + (long long)t*PSTR + tid*4;
#pragma unroll
            for (int j = 0; j < NO; j++)
                *(float4*)(op + j*BB) =
                    make_float4(acc[0][j],acc[1][j],acc[2][j],acc[3][j]);

            __threadfence();
            __syncthreads();
            if (tid == 0)
                asm volatile("st.release.gpu.global.b32 [%0], %1;"
                             :: "l"(&g_ready[t]), "r"(1u) : "memory");
        }
        return;
    }

    // ================= RECUR ROLE =================
    // 8 blocks x 4 warps (1 warp/SMSP). Each thread interleaves TWO
    // independent batch streams: stream chains overlap -> hides shfl/MUFU lat.
    const int rb   = bid - PREPB;
    const int lane = tid & 31;
    const int q    = lane & 3;                    // quad lane: gate f/i/o/-
    const int wid  = tid >> 5;
    const int b0   = rb*64 + wid*16 + ((lane >> 2) & 7);
    const int b1   = b0 + 8;

    int idx[8];
#pragma unroll
    for (int r = 0; r < 4; r++){ idx[2*r] = 2*(q^r); idx[2*r+1] = 2*(q^r)+1; }

    const float* gw = (q==0) ? Wf : ((q==1) ? Wi : Wo);
    float wg[8], wu0[8], wu1[8];
#pragma unroll
    for (int r = 0; r < 8; r++){
        wg[r]  = gw[DD + idx[r]];
        wu0[r] = Wu[(2*q  )*136 + DD + idx[r]];
        wu1[r] = Wu[(2*q+1)*136 + DD + idx[r]];
    }
    const float cg = cosf( (q==0) ? qwf[0] : ((q==1) ? qwi[0] : qwo[0]) );
    const int kg = (q < 3) ? q : 2;

    const float* __restrict__ preA = g_pre + b0;
    const float* __restrict__ preB = g_pre + b1;

    float h0[2] = {0.f,0.f}, h1[2] = {0.f,0.f};
    float c0[2] = {0.f,0.f}, c1[2] = {0.f,0.f};
    float pr[8][2][3];                             // [phase][stream][val]

    const unsigned m = 0xffffffffu;

    auto POLL = [&](int tbase){
        int tp = tbase + (lane & 7);
        if (tp > TT-1) tp = TT-1;
        const unsigned* fp = &g_ready[tp];
        unsigned v;
        do {
            asm volatile("ld.acquire.gpu.global.b32 %0, [%1];"
                         : "=r"(v) : "l"(fp) : "memory");
        } while (!__all_sync(m, v != 0));
        asm volatile("fence.acq_rel.gpu;" ::: "memory");
    };

    auto LOAD = [&](float p[2][3], int t){
        const long long off = (long long)t*PSTR;
        const float* a = preA + off;
        const float* bptr = preB + off;
        p[0][0] = __ldg(a    + kg*BB);
        p[1][0] = __ldg(bptr + kg*BB);
        p[0][1] = __ldg(a    + (3 + 2*q)*BB);
        p[1][1] = __ldg(bptr + (3 + 2*q)*BB);
        p[0][2] = __ldg(a    + (4 + 2*q)*BB);
        p[1][2] = __ldg(bptr + (4 + 2*q)*BB);
    };

    auto STEP2 = [&](int t, const float p[2][3]){
        // ---- allgather hx for BOTH streams (12 shfls, grouped) ----
        const float a0 = h0[0], a1 = h1[0], e0 = h0[1], e1 = h1[1];
        const float aw0 = __shfl_xor_sync(m, a0, 1);
        const float aw1 = __shfl_xor_sync(m, a1, 1);
        const float ew0 = __shfl_xor_sync(m, e0, 1);
        const float ew1 = __shfl_xor_sync(m, e1, 1);
        const float ax0 = __shfl_xor_sync(m, a0, 2);
        const float ax1 = __shfl_xor_sync(m, a1, 2);
        const float ex0 = __shfl_xor_sync(m, e0, 2);
        const float ex1 = __shfl_xor_sync(m, e1, 2);
        const float ay0 = __shfl_xor_sync(m, aw0, 2);
        const float ay1 = __shfl_xor_sync(m, aw1, 2);
        const float ey0 = __shfl_xor_sync(m, ew0, 2);
        const float ey1 = __shfl_xor_sync(m, ew1, 2);
        const float H[2][8] = {{a0,a1,aw0,aw1,ax0,ax1,ay0,ay1},
                               {e0,e1,ew0,ew1,ex0,ex1,ey0,ey1}};

        // ---- dots for both streams ----
        float zg[2], z0[2], z1[2];
#pragma unroll
        for (int s = 0; s < 2; s++){
            float g_ = p[s][0], u0 = p[s][1], u1 = p[s][2];
            float gA = 0.f, u0A = 0.f, u1A = 0.f;
#pragma unroll
            for (int r = 0; r < 8; r += 2){
                g_  = fmaf(wg [r],   H[s][r],   g_ );
                gA  = fmaf(wg [r+1], H[s][r+1], gA );
                u0  = fmaf(wu0[r],   H[s][r],   u0 );
                u0A = fmaf(wu0[r+1], H[s][r+1], u0A);
                u1  = fmaf(wu1[r],   H[s][r],   u1 );
                u1A = fmaf(wu1[r+1], H[s][r+1], u1A);
            }
            zg[s] = g_ + gA; z0[s] = u0 + u0A; z1[s] = u1 + u1A;
        }

        // ---- gates + g tanh for both streams ----
        float gate[2], g0[2], g1[2];
#pragma unroll
        for (int s = 0; s < 2; s++){
            gate[s] = sigm_poly(cg * __cosf(zg[s]));
            g0[s]   = tanh_fast(z0[s]);
            g1[s]   = tanh_fast(z1[s]);
        }

        // ---- broadcasts (6 shfls, grouped) ----
        const float fA = __shfl_sync(m, gate[0], 0, 4);
        const float iA = __shfl_sync(m, gate[0], 1, 4);
        const float oA = __shfl_sync(m, gate[0], 2, 4);
        const float fB = __shfl_sync(m, gate[1], 0, 4);
        const float iB = __shfl_sync(m, gate[1], 1, 4);
        const float oB = __shfl_sync(m, gate[1], 2, 4);
        const float f[2] = {fA, fB}, i[2] = {iA, iB}, o[2] = {oA, oB};

        // ---- state update + store, both streams ----
#pragma unroll
        for (int s = 0; s < 2; s++){
            c0[s] = fmaf(f[s], c0[s], i[s]*g0[s]);
            c1[s] = fmaf(f[s], c1[s], i[s]*g1[s]);
            h0[s] = o[s] * tanh_fast(c0[s]);
            h1[s] = o[s] * tanh_fast(c1[s]);
        }
        *(float2*)(out + ((long long)t*BB + b0)*8 + 2*q) = make_float2(h0[0], h1[0]);
        *(float2*)(out + ((long long)t*BB + b1)*8 + 2*q) = make_float2(h0[1], h1[1]);
    };

    POLL(0);
#pragma unroll
    for (int ph = 0; ph < 8; ph++) LOAD(pr[ph], ph);

    for (int tb = 0; tb < TT; tb += 8){
        POLL(tb + 8);                    // clamped inside; cheap when set
#pragma unroll
        for (int ph = 0; ph < 8; ph++){
            STEP2(tb + ph, pr[ph]);
            int tn = tb + ph + 8; if (tn >= TT) tn = TT - 1;
            LOAD(pr[ph], tn);
        }
    }

    if (write_tail){
        float* hp = out + (long long)TT*BB*8;
        *(float2*)(hp + b0*8 + 2*q)        = make_float2(h0[0], h1[0]);
        *(float2*)(hp + BB*8 + b0*8 + 2*q) = make_float2(c0[0], c1[0]);
        *(float2*)(hp + b1*8 + 2*q)        = make_float2(h0[1], h1[1]);
        *(float2*)(hp + BB*8 + b1*8 + 2*q) = make_float2(c0[1], c1[1]);
    }
}

// ---------------------------------------------------------------------------
extern "C" void kernel_launch(void* const* d_in, const int* in_sizes, int n_in,
                              void* d_out, int out_size)
{
    const float* x   = (const float*)d_in[0];
    const float* Wf  = (const float*)d_in[1];
    const float* bf  = (const float*)d_in[2];
    const float* Wi  = (const float*)d_in[3];
    const float* bi  = (const float*)d_in[4];
    const float* Wu  = (const float*)d_in[5];
    const float* bu  = (const float*)d_in[6];
    const float* Wo  = (const float*)d_in[7];
    const float* bo  = (const float*)d_in[8];
    const float* qwf = (const float*)d_in[9];
    const float* qwi = (const float*)d_in[10];
    // d_in[11] = qwu: unused — g path has no quantum gate in the reference
    const float* qwo = (const float*)d_in[12];
    float* out = (float*)d_out;

    const int write_tail = (out_size >= TT*BB*8 + 2*BB*8) ? 1 : 0;

    fused_kernel<<<PREPB + RECB, 128>>>(x, Wf, bf, Wi, bi, Wu, bu, Wo, bo,
                                        qwf, qwi, qwo, out, write_tail);
}

// round 8
// speedup vs baseline: 1.6243x; 1.2058x over previous
#include <cuda_runtime.h>

#define TT 1024
#define BB 512
#define DD 128
#define NO 11                 // 0=f,1=i,2=o,3..10=g0..g7
#define PSTR (NO*BB)
#define PREPB 256             // prep blocks (128 thr), REPS timesteps each
#define REPS 4
#define RECB 16               // recur blocks: 128 thr = 4 warps, 32 batch each

__device__ float g_pre[TT * NO * BB];     // ~23 MB scratch, [t][k][B]
__device__ unsigned g_ready[TT];          // zero-init at load; monotonic flags

__device__ __forceinline__ float f4c(const float4 v, int kk){
    return kk==0 ? v.x : kk==1 ? v.y : kk==2 ? v.z : v.w;
}

__device__ __forceinline__ float tanh_fast(float v){
    return 1.0f - __fdividef(2.0f, __expf(2.0f*v) + 1.0f);
}

// sigmoid(u), u in [-1,1]: 0.5 + u*P(u^2), Estrin, |err| ~ 2e-7
__device__ __forceinline__ float sigm_poly(float u){
    const float t  = u*u;
    const float E0 = fmaf(t, -2.0833334e-2f, 0.25f);
    const float E1 = fmaf(t, -2.10821e-4f,   2.0833334e-3f);
    const float E2 = fmaf(t, -2.16387e-6f,   2.13570e-5f);
    const float t2 = t*t;
    const float P  = fmaf(t2, fmaf(t2, E2, E1), E0);
    return fmaf(u, P, 0.5f);
}

__global__ void __launch_bounds__(128) fused_kernel(
    const float* __restrict__ x,
    const float* __restrict__ Wf, const float* __restrict__ bf,
    const float* __restrict__ Wi, const float* __restrict__ bi,
    const float* __restrict__ Wu, const float* __restrict__ bu,
    const float* __restrict__ Wo, const float* __restrict__ bo,
    const float* __restrict__ qwf, const float* __restrict__ qwi,
    const float* __restrict__ qwo,
    float* __restrict__ out, int write_tail)
{
    const int bid = blockIdx.x;
    const int tid = threadIdx.x;

    if (bid < PREPB){
        // ================= PREP ROLE (R4's proven version) =================
        __shared__ __align__(16) float wsm[DD*12];
        __shared__ float bsm[12];
        {
            const int k = tid;
            wsm[k*12+0] = Wf[k];
            wsm[k*12+1] = Wi[k];
            wsm[k*12+2] = Wo[k];
#pragma unroll
            for (int u = 0; u < 8; u++) wsm[k*12+3+u] = Wu[u*136 + k];
            wsm[k*12+11] = 0.0f;
            if (tid == 0){
                bsm[0] = bf[0]; bsm[1] = bi[0]; bsm[2] = bo[0];
                for (int u = 0; u < 8; u++) bsm[3+u] = bu[u];
                bsm[11] = 0.0f;
            }
        }
        __syncthreads();

        for (int rep = 0; rep < REPS; rep++){
            const int t = bid + rep*PREPB;          // low t finish first
            const float4* __restrict__ xp =
                (const float4*)x + ((long long)t*BB + tid*4)*(DD/4);

            float acc[4][NO];
#pragma unroll
            for (int r = 0; r < 4; r++)
#pragma unroll
                for (int j = 0; j < NO; j++) acc[r][j] = bsm[j];

#pragma unroll 2
            for (int c = 0; c < 32; c++){
                float4 xv[4];
#pragma unroll
                for (int r = 0; r < 4; r++) xv[r] = xp[r*32 + c];
#pragma unroll
                for (int kk = 0; kk < 4; kk++){
                    const int k = c*4 + kk;
                    const float4* wr = (const float4*)&wsm[k*12];
                    const float4 wa = wr[0], wb = wr[1], wc = wr[2];
                    const float w[NO] = {wa.x,wa.y,wa.z,wa.w,
                                         wb.x,wb.y,wb.z,wb.w,
                                         wc.x,wc.y,wc.z};
#pragma unroll
                    for (int r = 0; r < 4; r++){
                        const float xs = f4c(xv[r], kk);
#pragma unroll
                        for (int j = 0; j < NO; j++)
                            acc[r][j] = fmaf(xs, w[j], acc[r][j]);
                    }
                }
            }

            float* op = g_pre + (long long)t*PSTR + tid*4;
#pragma unroll
            for (int j = 0; j < NO; j++)
                *(float4*)(op + j*BB) =
                    make_float4(acc[0][j],acc[1][j],acc[2][j],acc[3][j]);

            __threadfence();
            __syncthreads();
            if (tid == 0)
                asm volatile("st.release.gpu.global.b32 [%0], %1;"
                             :: "l"(&g_ready[t]), "r"(1u) : "memory");
        }
        return;
    }

    // ================= RECUR ROLE =================
    // 16 blocks x 4 warps (1 warp/SMSP), 4 threads per batch element.
    // Every lane computes ALL THREE gates redundantly -> no gate broadcast
    // shfl on the critical chain. Lane q owns hidden lanes {2q, 2q+1}.
    const int rb   = bid - PREPB;
    const int lane = tid & 31;
    const int q    = lane & 3;
    const int b    = rb*32 + (tid >> 2);

    // H-register order after allgather: H[2r..2r+1] = h[2*(q^r)], h[2*(q^r)+1]
    int idx[8];
#pragma unroll
    for (int r = 0; r < 4; r++){ idx[2*r] = 2*(q^r); idx[2*r+1] = 2*(q^r)+1; }

    float wf8[8], wi8[8], wo8[8], wu0[8], wu1[8];
#pragma unroll
    for (int r = 0; r < 8; r++){
        wf8[r] = Wf[DD + idx[r]];
        wi8[r] = Wi[DD + idx[r]];
        wo8[r] = Wo[DD + idx[r]];
        wu0[r] = Wu[(2*q  )*136 + DD + idx[r]];
        wu1[r] = Wu[(2*q+1)*136 + DD + idx[r]];
    }
    const float cgf = cosf(qwf[0]);
    const float cgi = cosf(qwi[0]);
    const float cgo = cosf(qwo[0]);

    const float* __restrict__ pre = g_pre + b;

    float h0 = 0.f, h1 = 0.f, c0 = 0.f, c1 = 0.f;
    float pr[8][5];                       // [phase][f,i,o,g2q,g2q+1]

    const unsigned m = 0xffffffffu;

    auto POLL = [&](int tbase){
        int tp = tbase + (lane & 7);
        if (tp > TT-1) tp = TT-1;
        const unsigned* fp = &g_ready[tp];
        unsigned v;
        do {
            asm volatile("ld.acquire.gpu.global.b32 %0, [%1];"
                         : "=r"(v) : "l"(fp) : "memory");
        } while (!__all_sync(m, v != 0));
        asm volatile("fence.acq_rel.gpu;" ::: "memory");
    };

    auto LOAD = [&](float* p, int t){
        const float* base = pre + (long long)t*PSTR;
        p[0] = __ldg(base);               // f pre-activation
        p[1] = __ldg(base + BB);          // i
        p[2] = __ldg(base + 2*BB);        // o
        p[3] = __ldg(base + (3 + 2*q)*BB);
        p[4] = __ldg(base + (4 + 2*q)*BB);
    };

    auto STEP = [&](int t, const float* p){
        // allgather hx across the quad (6 shfls, 2 levels)
        const float v0 = h0, v1 = h1;
        const float w0 = __shfl_xor_sync(m, v0, 1);
        const float w1 = __shfl_xor_sync(m, v1, 1);
        const float x0 = __shfl_xor_sync(m, v0, 2);
        const float x1 = __shfl_xor_sync(m, v1, 2);
        const float y0 = __shfl_xor_sync(m, w0, 2);
        const float y1 = __shfl_xor_sync(m, w1, 2);
        const float H[8] = {v0, v1, w0, w1, x0, x1, y0, y1};

        // 5 dots (f, i, o, my two g lanes), dual accumulators
        float zf = p[0], zi = p[1], zo = p[2], z0 = p[3], z1 = p[4];
        float zfA = 0.f, ziA = 0.f, zoA = 0.f, z0A = 0.f, z1A = 0.f;
#pragma unroll
        for (int r = 0; r < 8; r += 2){
            zf  = fmaf(wf8[r],   H[r],   zf );
            zfA = fmaf(wf8[r+1], H[r+1], zfA);
            zi  = fmaf(wi8[r],   H[r],   zi );
            ziA = fmaf(wi8[r+1], H[r+1], ziA);
            zo  = fmaf(wo8[r],   H[r],   zo );
            zoA = fmaf(wo8[r+1], H[r+1], zoA);
            z0  = fmaf(wu0[r],   H[r],   z0 );
            z0A = fmaf(wu0[r+1], H[r+1], z0A);
            z1  = fmaf(wu1[r],   H[r],   z1 );
            z1A = fmaf(wu1[r+1], H[r+1], z1A);
        }
        zf += zfA; zi += ziA; zo += zoA; z0 += z0A; z1 += z1A;

        // all gates computed locally — no cross-lane dependency
        const float f = sigm_poly(cgf * __cosf(zf));
        const float i = sigm_poly(cgi * __cosf(zi));
        const float o = sigm_poly(cgo * __cosf(zo));
        const float g0 = tanh_fast(z0);
        const float g1 = tanh_fast(z1);

        c0 = fmaf(f, c0, i*g0);
        c1 = fmaf(f, c1, i*g1);
        h0 = o * tanh_fast(c0);
        h1 = o * tanh_fast(c1);

        *(float2*)(out + ((long long)t*BB + b)*8 + 2*q) = make_float2(h0, h1);
    };

    POLL(0);
#pragma unroll
    for (int ph = 0; ph < 8; ph++) LOAD(pr[ph], ph);

    for (int tb = 0; tb < TT; tb += 8){
        POLL(tb + 8);                    // clamped inside; cheap when set
#pragma unroll
        for (int ph = 0; ph < 8; ph++){
            STEP(tb + ph, pr[ph]);
            int tn = tb + ph + 8; if (tn >= TT) tn = TT - 1;
            LOAD(pr[ph], tn);
        }
    }

    if (write_tail){
        float* hp = out + (long long)TT*BB*8;
        *(float2*)(hp + b*8 + 2*q)        = make_float2(h0, h1);
        *(float2*)(hp + BB*8 + b*8 + 2*q) = make_float2(c0, c1);
    }
}

// ---------------------------------------------------------------------------
extern "C" void kernel_launch(void* const* d_in, const int* in_sizes, int n_in,
                              void* d_out, int out_size)
{
    const float* x   = (const float*)d_in[0];
    const float* Wf  = (const float*)d_in[1];
    const float* bf  = (const float*)d_in[2];
    const float* Wi  = (const float*)d_in[3];
    const float* bi  = (const float*)d_in[4];
    const float* Wu  = (const float*)d_in[5];
    const float* bu  = (const float*)d_in[6];
    const float* Wo  = (const float*)d_in[7];
    const float* bo  = (const float*)d_in[8];
    const float* qwf = (const float*)d_in[9];
    const float* qwi = (const float*)d_in[10];
    // d_in[11] = qwu: unused — g path has no quantum gate in the reference
    const float* qwo = (const float*)d_in[12];
    float* out = (float*)d_out;

    const int write_tail = (out_size >= TT*BB*8 + 2*BB*8) ? 1 : 0;

    fused_kernel<<<PREPB + RECB, 128>>>(x, Wf, bf, Wi, bi, Wu, bu, Wo, bo,
                                        qwf, qwi, qwo, out, write_tail);
}

// round 9
// speedup vs baseline: 1.6580x; 1.0208x over previous
#include <cuda_runtime.h>

#define TT 1024
#define BB 512
#define DD 128
#define NO 11                 // 0=f,1=i,2=o,3..10=g0..g7
#define PSTR (NO*BB)
#define PREPB 256             // prep blocks (128 thr), REPS timesteps each
#define REPS 4
#define RECB 32               // recur blocks: 128 thr = 4 warps, 16 batch each

__device__ float g_pre[TT * NO * BB];     // ~23 MB scratch, [t][k][B]
__device__ unsigned g_ready[TT];          // zero-init at load; monotonic flags

__device__ __forceinline__ float f4c(const float4 v, int kk){
    return kk==0 ? v.x : kk==1 ? v.y : kk==2 ? v.z : v.w;
}

__device__ __forceinline__ float tanh_fast(float v){
    return 1.0f - __fdividef(2.0f, __expf(2.0f*v) + 1.0f);
}

// sigmoid(u), u in [-1,1]: 0.5 + u*P(u^2), Estrin, |err| ~ 2e-7
__device__ __forceinline__ float sigm_poly(float u){
    const float t  = u*u;
    const float E0 = fmaf(t, -2.0833334e-2f, 0.25f);
    const float E1 = fmaf(t, -2.10821e-4f,   2.0833334e-3f);
    const float E2 = fmaf(t, -2.16387e-6f,   2.13570e-5f);
    const float t2 = t*t;
    const float P  = fmaf(t2, fmaf(t2, E2, E1), E0);
    return fmaf(u, P, 0.5f);
}

__global__ void __launch_bounds__(128) fused_kernel(
    const float* __restrict__ x,
    const float* __restrict__ Wf, const float* __restrict__ bf,
    const float* __restrict__ Wi, const float* __restrict__ bi,
    const float* __restrict__ Wu, const float* __restrict__ bu,
    const float* __restrict__ Wo, const float* __restrict__ bo,
    const float* __restrict__ qwf, const float* __restrict__ qwi,
    const float* __restrict__ qwo,
    float* __restrict__ out, int write_tail)
{
    const int bid = blockIdx.x;
    const int tid = threadIdx.x;

    if (bid < PREPB){
        // ================= PREP ROLE (proven, unchanged) =================
        __shared__ __align__(16) float wsm[DD*12];
        __shared__ float bsm[12];
        {
            const int k = tid;
            wsm[k*12+0] = Wf[k];
            wsm[k*12+1] = Wi[k];
            wsm[k*12+2] = Wo[k];
#pragma unroll
            for (int u = 0; u < 8; u++) wsm[k*12+3+u] = Wu[u*136 + k];
            wsm[k*12+11] = 0.0f;
            if (tid == 0){
                bsm[0] = bf[0]; bsm[1] = bi[0]; bsm[2] = bo[0];
                for (int u = 0; u < 8; u++) bsm[3+u] = bu[u];
                bsm[11] = 0.0f;
            }
        }
        __syncthreads();

        for (int rep = 0; rep < REPS; rep++){
            const int t = bid + rep*PREPB;          // low t finish first
            const float4* __restrict__ xp =
                (const float4*)x + ((long long)t*BB + tid*4)*(DD/4);

            float acc[4][NO];
#pragma unroll
            for (int r = 0; r < 4; r++)
#pragma unroll
                for (int j = 0; j < NO; j++) acc[r][j] = bsm[j];

#pragma unroll 2
            for (int c = 0; c < 32; c++){
                float4 xv[4];
#pragma unroll
                for (int r = 0; r < 4; r++) xv[r] = xp[r*32 + c];
#pragma unroll
                for (int kk = 0; kk < 4; kk++){
                    const int k = c*4 + kk;
                    const float4* wr = (const float4*)&wsm[k*12];
                    const float4 wa = wr[0], wb = wr[1], wc = wr[2];
                    const float w[NO] = {wa.x,wa.y,wa.z,wa.w,
                                         wb.x,wb.y,wb.z,wb.w,
                                         wc.x,wc.y,wc.z};
#pragma unroll
                    for (int r = 0; r < 4; r++){
                        const float xs = f4c(xv[r], kk);
#pragma unroll
                        for (int j = 0; j < NO; j++)
                            acc[r][j] = fmaf(xs, w[j], acc[r][j]);
                    }
                }
            }

            float* op = g_pre + (long long)t*PSTR + tid*4;
#pragma unroll
            for (int j = 0; j < NO; j++)
                *(float4*)(op + j*BB) =
                    make_float4(acc[0][j],acc[1][j],acc[2][j],acc[3][j]);

            __threadfence();
            __syncthreads();
            if (tid == 0)
                asm volatile("st.release.gpu.global.b32 [%0], %1;"
                             :: "l"(&g_ready[t]), "r"(1u) : "memory");
        }
        return;
    }

    // ================= RECUR ROLE =================
    // 32 blocks x 4 warps (1 warp/SMSP, 32 SMs). 8 threads per batch element;
    // each thread owns ONE hidden lane. All three gates computed redundantly
    // per lane (no gate broadcast). Butterfly allgather: H[k] = h[q^k].
    const int rb   = bid - PREPB;
    const int lane = tid & 31;
    const int q    = lane & 7;                 // my hidden lane
    const int b    = rb*16 + (tid >> 3);       // 16 batches per block

    float wf8[8], wi8[8], wo8[8], wu8[8];
#pragma unroll
    for (int r = 0; r < 8; r++){
        const int hr = q ^ r;                  // H[r] = h[q^r]
        wf8[r] = Wf[DD + hr];
        wi8[r] = Wi[DD + hr];
        wo8[r] = Wo[DD + hr];
        wu8[r] = Wu[q*136 + DD + hr];          // my g row
    }
    const float cgf = cosf(qwf[0]);
    const float cgi = cosf(qwi[0]);
    const float cgo = cosf(qwo[0]);

    const float* __restrict__ pre = g_pre + b;

    float h = 0.f, c = 0.f;
    float pr[8][4];                            // [phase][f,i,o,g_q]

    const unsigned m = 0xffffffffu;

    auto POLL = [&](int tbase){
        int tp = tbase + (lane & 7);
        if (tp > TT-1) tp = TT-1;
        const unsigned* fp = &g_ready[tp];
        unsigned v;
        do {
            asm volatile("ld.acquire.gpu.global.b32 %0, [%1];"
                         : "=r"(v) : "l"(fp) : "memory");
        } while (!__all_sync(m, v != 0));
        asm volatile("fence.acq_rel.gpu;" ::: "memory");
    };

    auto LOAD = [&](float* p, int t){
        const float* base = pre + (long long)t*PSTR;
        p[0] = __ldg(base);                    // f pre-activation
        p[1] = __ldg(base + BB);               // i
        p[2] = __ldg(base + 2*BB);             // o
        p[3] = __ldg(base + (3 + q)*BB);       // my g row
    };

    auto STEP = [&](int t, const float* p){
        // butterfly allgather of h across the 8-lane group (7 shfls, 3 levels)
        const float H0 = h;
        const float H1 = __shfl_xor_sync(m, H0, 1);
        const float H2 = __shfl_xor_sync(m, H0, 2);
        const float H3 = __shfl_xor_sync(m, H1, 2);
        const float H4 = __shfl_xor_sync(m, H0, 4);
        const float H5 = __shfl_xor_sync(m, H1, 4);
        const float H6 = __shfl_xor_sync(m, H2, 4);
        const float H7 = __shfl_xor_sync(m, H3, 4);
        const float H[8] = {H0, H1, H2, H3, H4, H5, H6, H7};

        // 4 local dots (f, i, o, my g), dual accumulators
        float zf = p[0], zi = p[1], zo = p[2], zg = p[3];
        float zfA = 0.f, ziA = 0.f, zoA = 0.f, zgA = 0.f;
#pragma unroll
        for (int r = 0; r < 8; r += 2){
            zf  = fmaf(wf8[r],   H[r],   zf );
            zfA = fmaf(wf8[r+1], H[r+1], zfA);
            zi  = fmaf(wi8[r],   H[r],   zi );
            ziA = fmaf(wi8[r+1], H[r+1], ziA);
            zo  = fmaf(wo8[r],   H[r],   zo );
            zoA = fmaf(wo8[r+1], H[r+1], zoA);
            zg  = fmaf(wu8[r],   H[r],   zg );
            zgA = fmaf(wu8[r+1], H[r+1], zgA);
        }
        zf += zfA; zi += ziA; zo += zoA; zg += zgA;

        const float f = sigm_poly(cgf * __cosf(zf));
        const float i = sigm_poly(cgi * __cosf(zi));
        const float o = sigm_poly(cgo * __cosf(zo));
        const float g = tanh_fast(zg);

        c = fmaf(f, c, i*g);
        h = o * tanh_fast(c);

        out[((long long)t*BB + b)*8 + q] = h;   // warp: 128B contiguous
    };

    POLL(0);
#pragma unroll
    for (int ph = 0; ph < 8; ph++) LOAD(pr[ph], ph);

    for (int tb = 0; tb < TT; tb += 8){
        POLL(tb + 8);                    // clamped inside; cheap when set
#pragma unroll
        for (int ph = 0; ph < 8; ph++){
            STEP(tb + ph, pr[ph]);
            int tn = tb + ph + 8; if (tn >= TT) tn = TT - 1;
            LOAD(pr[ph], tn);
        }
    }

    if (write_tail){
        float* hp = out + (long long)TT*BB*8;
        hp[b*8 + q]         = h;
        hp[BB*8 + b*8 + q]  = c;
    }
}

// ---------------------------------------------------------------------------
extern "C" void kernel_launch(void* const* d_in, const int* in_sizes, int n_in,
                              void* d_out, int out_size)
{
    const float* x   = (const float*)d_in[0];
    const float* Wf  = (const float*)d_in[1];
    const float* bf  = (const float*)d_in[2];
    const float* Wi  = (const float*)d_in[3];
    const float* bi  = (const float*)d_in[4];
    const float* Wu  = (const float*)d_in[5];
    const float* bu  = (const float*)d_in[6];
    const float* Wo  = (const float*)d_in[7];
    const float* bo  = (const float*)d_in[8];
    const float* qwf = (const float*)d_in[9];
    const float* qwi = (const float*)d_in[10];
    // d_in[11] = qwu: unused — g path has no quantum gate in the reference
    const float* qwo = (const float*)d_in[12];
    float* out = (float*)d_out;

    const int write_tail = (out_size >= TT*BB*8 + 2*BB*8) ? 1 : 0;

    fused_kernel<<<PREPB + RECB, 128>>>(x, Wf, bf, Wi, bi, Wu, bu, Wo, bo,
                                        qwf, qwi, qwo, out, write_tail);
}

// round 10
// speedup vs baseline: 1.6831x; 1.0151x over previous
#include <cuda_runtime.h>

#define TT 1024
#define BB 512
#define DD 128
#define NO 11                 // 0=f,1=i,2=o,3..10=g0..g7
#define PSTR (NO*BB)
#define PREPB 256             // prep blocks (128 thr), REPS timesteps each
#define REPS 4
#define RECB 32               // recur blocks: 128 thr = 4 warps, 16 batch each

__device__ float g_pre[TT * NO * BB];     // ~23 MB scratch, [t][k][B]
__device__ unsigned g_ready[TT];          // zero-init at load; monotonic flags

__device__ __forceinline__ float f4c(const float4 v, int kk){
    return kk==0 ? v.x : kk==1 ? v.y : kk==2 ? v.z : v.w;
}

__device__ __forceinline__ float tanh_fast(float v){
    return 1.0f - __fdividef(2.0f, __expf(2.0f*v) + 1.0f);
}

// sigmoid(u), u in [-1,1]: 0.5 + u*P(u^2), Estrin, |err| ~ 2e-7
__device__ __forceinline__ float sigm_poly(float u){
    const float t  = u*u;
    const float E0 = fmaf(t, -2.0833334e-2f, 0.25f);
    const float E1 = fmaf(t, -2.10821e-4f,   2.0833334e-3f);
    const float E2 = fmaf(t, -2.16387e-6f,   2.13570e-5f);
    const float t2 = t*t;
    const float P  = fmaf(t2, fmaf(t2, E2, E1), E0);
    return fmaf(u, P, 0.5f);
}

__device__ __forceinline__ unsigned flag_acq(const unsigned* fp){
    unsigned v;
    asm volatile("ld.acquire.gpu.global.b32 %0, [%1];"
                 : "=r"(v) : "l"(fp) : "memory");
    return v;
}

__global__ void __launch_bounds__(128) fused_kernel(
    const float* __restrict__ x,
    const float* __restrict__ Wf, const float* __restrict__ bf,
    const float* __restrict__ Wi, const float* __restrict__ bi,
    const float* __restrict__ Wu, const float* __restrict__ bu,
    const float* __restrict__ Wo, const float* __restrict__ bo,
    const float* __restrict__ qwf, const float* __restrict__ qwi,
    const float* __restrict__ qwo,
    float* __restrict__ out, int write_tail)
{
    const int bid = blockIdx.x;
    const int tid = threadIdx.x;

    if (bid < PREPB){
        // ================= PREP ROLE (proven, unchanged) =================
        __shared__ __align__(16) float wsm[DD*12];
        __shared__ float bsm[12];
        {
            const int k = tid;
            wsm[k*12+0] = Wf[k];
            wsm[k*12+1] = Wi[k];
            wsm[k*12+2] = Wo[k];
#pragma unroll
            for (int u = 0; u < 8; u++) wsm[k*12+3+u] = Wu[u*136 + k];
            wsm[k*12+11] = 0.0f;
            if (tid == 0){
                bsm[0] = bf[0]; bsm[1] = bi[0]; bsm[2] = bo[0];
                for (int u = 0; u < 8; u++) bsm[3+u] = bu[u];
                bsm[11] = 0.0f;
            }
        }
        __syncthreads();

        for (int rep = 0; rep < REPS; rep++){
            const int t = bid + rep*PREPB;          // low t finish first
            const float4* __restrict__ xp =
                (const float4*)x + ((long long)t*BB + tid*4)*(DD/4);

            float acc[4][NO];
#pragma unroll
            for (int r = 0; r < 4; r++)
#pragma unroll
                for (int j = 0; j < NO; j++) acc[r][j] = bsm[j];

#pragma unroll 2
            for (int c = 0; c < 32; c++){
                float4 xv[4];
#pragma unroll
                for (int r = 0; r < 4; r++) xv[r] = xp[r*32 + c];
#pragma unroll
                for (int kk = 0; kk < 4; kk++){
                    const int k = c*4 + kk;
                    const float4* wr = (const float4*)&wsm[k*12];
                    const float4 wa = wr[0], wb = wr[1], wc = wr[2];
                    const float w[NO] = {wa.x,wa.y,wa.z,wa.w,
                                         wb.x,wb.y,wb.z,wb.w,
                                         wc.x,wc.y,wc.z};
#pragma unroll
                    for (int r = 0; r < 4; r++){
                        const float xs = f4c(xv[r], kk);
#pragma unroll
                        for (int j = 0; j < NO; j++)
                            acc[r][j] = fmaf(xs, w[j], acc[r][j]);
                    }
                }
            }

            float* op = g_pre + (long long)t*PSTR + tid*4;
#pragma unroll
            for (int j = 0; j < NO; j++)
                *(float4*)(op + j*BB) =
                    make_float4(acc[0][j],acc[1][j],acc[2][j],acc[3][j]);

            __threadfence();
            __syncthreads();
            if (tid == 0)
                asm volatile("st.release.gpu.global.b32 [%0], %1;"
                             :: "l"(&g_ready[t]), "r"(1u) : "memory");
        }
        return;
    }

    // ================= RECUR ROLE =================
    // 32 blocks x 4 warps. 8 threads per batch element; each thread owns ONE
    // hidden lane. Redundant gates (no broadcast). Butterfly allgather.
    // Flag polling is software-pipelined one group ahead: zero exposed
    // latency on the fast path, no MEMBAR.
    const int rb   = bid - PREPB;
    const int lane = tid & 31;
    const int q    = lane & 7;                 // my hidden lane
    const int b    = rb*16 + (tid >> 3);       // 16 batches per block

    float wf8[8], wi8[8], wo8[8], wu8[8];
#pragma unroll
    for (int r = 0; r < 8; r++){
        const int hr = q ^ r;                  // H[r] = h[q^r]
        wf8[r] = Wf[DD + hr];
        wi8[r] = Wi[DD + hr];
        wo8[r] = Wo[DD + hr];
        wu8[r] = Wu[q*136 + DD + hr];          // my g row
    }
    const float cgf = cosf(qwf[0]);
    const float cgi = cosf(qwi[0]);
    const float cgo = cosf(qwo[0]);

    const float* __restrict__ pre = g_pre + b;

    float h = 0.f, c = 0.f;
    float pr[8][4];                            // [phase][f,i,o,g_q]

    const unsigned m = 0xffffffffu;

    // my flag slot within a group of 8 timesteps
    auto FLAG_ADDR = [&](int tbase) -> const unsigned* {
        int tp = tbase + (lane & 7);
        if (tp > TT-1) tp = TT-1;
        return &g_ready[tp];
    };

    auto POLL_BLOCK = [&](int tbase){          // blocking (startup/slow path)
        const unsigned* fp = FLAG_ADDR(tbase);
        unsigned v;
        do { v = flag_acq(fp); } while (!__all_sync(m, v != 0));
    };

    auto LOAD = [&](float* p, int t){
        const float* base = pre + (long long)t*PSTR;
        p[0] = __ldg(base);                    // f pre-activation
        p[1] = __ldg(base + BB);               // i
        p[2] = __ldg(base + 2*BB);             // o
        p[3] = __ldg(base + (3 + q)*BB);       // my g row
    };

    auto STEP = [&](int t, const float* p){
        // butterfly allgather of h across the 8-lane group (7 shfls)
        const float H0 = h;
        const float H1 = __shfl_xor_sync(m, H0, 1);
        const float H2 = __shfl_xor_sync(m, H0, 2);
        const float H3 = __shfl_xor_sync(m, H1, 2);
        const float H4 = __shfl_xor_sync(m, H0, 4);
        const float H5 = __shfl_xor_sync(m, H1, 4);
        const float H6 = __shfl_xor_sync(m, H2, 4);
        const float H7 = __shfl_xor_sync(m, H3, 4);
        const float H[8] = {H0, H1, H2, H3, H4, H5, H6, H7};

        // 4 local dots (f, i, o, my g), dual accumulators
        float zf = p[0], zi = p[1], zo = p[2], zg = p[3];
        float zfA = 0.f, ziA = 0.f, zoA = 0.f, zgA = 0.f;
#pragma unroll
        for (int r = 0; r < 8; r += 2){
            zf  = fmaf(wf8[r],   H[r],   zf );
            zfA = fmaf(wf8[r+1], H[r+1], zfA);
            zi  = fmaf(wi8[r],   H[r],   zi );
            ziA = fmaf(wi8[r+1], H[r+1], ziA);
            zo  = fmaf(wo8[r],   H[r],   zo );
            zoA = fmaf(wo8[r+1], H[r+1], zoA);
            zg  = fmaf(wu8[r],   H[r],   zg );
            zgA = fmaf(wu8[r+1], H[r+1], zgA);
        }
        zf += zfA; zi += ziA; zo += zoA; zg += zgA;

        const float f = sigm_poly(cgf * __cosf(zf));
        const float i = sigm_poly(cgi * __cosf(zi));
        const float o = sigm_poly(cgo * __cosf(zo));
        const float g = tanh_fast(zg);

        c = fmaf(f, c, i*g);
        h = o * tanh_fast(c);

        out[((long long)t*BB + b)*8 + q] = h;   // warp: 128B contiguous
    };

    // Startup: block on group 0, prime ring, prefetch flag for group 8.
    POLL_BLOCK(0);
#pragma unroll
    for (int ph = 0; ph < 8; ph++) LOAD(pr[ph], ph);
    unsigned fv = flag_acq(FLAG_ADDR(8));       // pipelined flag for tb=0 check

    for (int tb = 0; tb < TT; tb += 8){
        // fv covers flags for group tb+8 (loaded one iteration ago)
        if (!__all_sync(m, fv != 0))
            POLL_BLOCK(tb + 8);                 // rare slow path
        fv = flag_acq(FLAG_ADDR(tb + 16));      // prefetch next group's flags
#pragma unroll
        for (int ph = 0; ph < 8; ph++){
            STEP(tb + ph, pr[ph]);
            int tn = tb + ph + 8; if (tn >= TT) tn = TT - 1;
            LOAD(pr[ph], tn);
        }
    }

    if (write_tail){
        float* hp = out + (long long)TT*BB*8;
        hp[b*8 + q]         = h;
        hp[BB*8 + b*8 + q]  = c;
    }
}

// ---------------------------------------------------------------------------
extern "C" void kernel_launch(void* const* d_in, const int* in_sizes, int n_in,
                              void* d_out, int out_size)
{
    const float* x   = (const float*)d_in[0];
    const float* Wf  = (const float*)d_in[1];
    const float* bf  = (const float*)d_in[2];
    const float* Wi  = (const float*)d_in[3];
    const float* bi  = (const float*)d_in[4];
    const float* Wu  = (const float*)d_in[5];
    const float* bu  = (const float*)d_in[6];
    const float* Wo  = (const float*)d_in[7];
    const float* bo  = (const float*)d_in[8];
    const float* qwf = (const float*)d_in[9];
    const float* qwi = (const float*)d_in[10];
    // d_in[11] = qwu: unused — g path has no quantum gate in the reference
    const float* qwo = (const float*)d_in[12];
    float* out = (float*)d_out;

    const int write_tail = (out_size >= TT*BB*8 + 2*BB*8) ? 1 : 0;

    fused_kernel<<<PREPB + RECB, 128>>>(x, Wf, bf, Wi, bi, Wu, bu, Wo, bo,
                                        qwf, qwi, qwo, out, write_tail);
}

// round 11
// speedup vs baseline: 2.2978x; 1.3652x over previous
#include <cuda_runtime.h>

#define TT 1024
#define BB 512
#define DD 128
#define NO 11                 // 0=f,1=i,2=o,3..10=g0..g7
#define PSTR (NO*BB)
#define PREPB 256             // prep blocks (128 thr), REPS timesteps each
#define REPS 4
#define RECB 32               // recur blocks: 128 thr = 4 warps, 16 batch each

__device__ float g_pre[TT * NO * BB];     // ~23 MB scratch, [t][k][B]
__device__ unsigned g_ready[TT];          // zero-init at load; monotonic flags

__device__ __forceinline__ float f4c(const float4 v, int kk){
    return kk==0 ? v.x : kk==1 ? v.y : kk==2 ? v.z : v.w;
}

__device__ __forceinline__ float tanh_fast(float v){
    return 1.0f - __fdividef(2.0f, __expf(2.0f*v) + 1.0f);
}

// sigmoid(u), u in [-1,1]: 0.5 + u*P(u^2), Estrin, |err| ~ 2e-7
__device__ __forceinline__ float sigm_poly(float u){
    const float t  = u*u;
    const float E0 = fmaf(t, -2.0833334e-2f, 0.25f);
    const float E1 = fmaf(t, -2.10821e-4f,   2.0833334e-3f);
    const float E2 = fmaf(t, -2.16387e-6f,   2.13570e-5f);
    const float t2 = t*t;
    const float P  = fmaf(t2, fmaf(t2, E2, E1), E0);
    return fmaf(u, P, 0.5f);
}

__device__ __forceinline__ unsigned flag_acq(const unsigned* fp){
    unsigned v;
    asm volatile("ld.acquire.gpu.global.b32 %0, [%1];"
                 : "=r"(v) : "l"(fp) : "memory");
    return v;
}

__global__ void __launch_bounds__(128) fused_kernel(
    const float* __restrict__ x,
    const float* __restrict__ Wf, const float* __restrict__ bf,
    const float* __restrict__ Wi, const float* __restrict__ bi,
    const float* __restrict__ Wu, const float* __restrict__ bu,
    const float* __restrict__ Wo, const float* __restrict__ bo,
    const float* __restrict__ qwf, const float* __restrict__ qwi,
    const float* __restrict__ qwo,
    float* __restrict__ out, int write_tail)
{
    const int bid = blockIdx.x;
    const int tid = threadIdx.x;

    if (bid < PREPB){
        // ================= PREP ROLE (proven, unchanged) =================
        __shared__ __align__(16) float wsm[DD*12];
        __shared__ float bsm[12];
        {
            const int k = tid;
            wsm[k*12+0] = Wf[k];
            wsm[k*12+1] = Wi[k];
            wsm[k*12+2] = Wo[k];
#pragma unroll
            for (int u = 0; u < 8; u++) wsm[k*12+3+u] = Wu[u*136 + k];
            wsm[k*12+11] = 0.0f;
            if (tid == 0){
                bsm[0] = bf[0]; bsm[1] = bi[0]; bsm[2] = bo[0];
                for (int u = 0; u < 8; u++) bsm[3+u] = bu[u];
                bsm[11] = 0.0f;
            }
        }
        __syncthreads();

        for (int rep = 0; rep < REPS; rep++){
            const int t = bid + rep*PREPB;          // low t finish first
            const float4* __restrict__ xp =
                (const float4*)x + ((long long)t*BB + tid*4)*(DD/4);

            float acc[4][NO];
#pragma unroll
            for (int r = 0; r < 4; r++)
#pragma unroll
                for (int j = 0; j < NO; j++) acc[r][j] = bsm[j];

#pragma unroll 2
            for (int c = 0; c < 32; c++){
                float4 xv[4];
#pragma unroll
                for (int r = 0; r < 4; r++) xv[r] = xp[r*32 + c];
#pragma unroll
                for (int kk = 0; kk < 4; kk++){
                    const int k = c*4 + kk;
                    const float4* wr = (const float4*)&wsm[k*12];
                    const float4 wa = wr[0], wb = wr[1], wc = wr[2];
                    const float w[NO] = {wa.x,wa.y,wa.z,wa.w,
                                         wb.x,wb.y,wb.z,wb.w,
                                         wc.x,wc.y,wc.z};
#pragma unroll
                    for (int r = 0; r < 4; r++){
                        const float xs = f4c(xv[r], kk);
#pragma unroll
                        for (int j = 0; j < NO; j++)
                            acc[r][j] = fmaf(xs, w[j], acc[r][j]);
                    }
                }
            }

            float* op = g_pre + (long long)t*PSTR + tid*4;
#pragma unroll
            for (int j = 0; j < NO; j++)
                *(float4*)(op + j*BB) =
                    make_float4(acc[0][j],acc[1][j],acc[2][j],acc[3][j]);

            __threadfence();
            __syncthreads();
            if (tid == 0)
                asm volatile("st.release.gpu.global.b32 [%0], %1;"
                             :: "l"(&g_ready[t]), "r"(1u) : "memory");
        }
        return;
    }

    // ================= RECUR ROLE =================
    // 32 blocks x 4 warps. 8 threads per batch element, each owns ONE hidden
    // lane. Redundant gates (no broadcast). The h allgather goes through a
    // per-warp SMEM row (STS + syncwarp + 2x LDS.128 broadcast) instead of a
    // 3-level shfl butterfly: chain ~60 cyc vs ~150. Double-buffered by step
    // parity so one syncwarp per step suffices.
    __shared__ __align__(16) float hxch[2][4][32];   // [buf][warp][lane]

    const int rb   = bid - PREPB;
    const int lane = tid & 31;
    const int wrp  = tid >> 5;
    const int q    = lane & 7;                 // my hidden lane
    const int b    = rb*16 + (tid >> 3);       // 16 batches per block

    // Natural-order weights (same for all lanes in a group; uniform-friendly)
    float wf8[8], wi8[8], wo8[8], wu8[8];
#pragma unroll
    for (int r = 0; r < 8; r++){
        wf8[r] = Wf[DD + r];
        wi8[r] = Wi[DD + r];
        wo8[r] = Wo[DD + r];
        wu8[r] = Wu[q*136 + DD + r];           // my g row
    }
    const float cgf = cosf(qwf[0]);
    const float cgi = cosf(qwi[0]);
    const float cgo = cosf(qwo[0]);

    const float* __restrict__ pre = g_pre + b;

    float h = 0.f, c = 0.f;
    float pr[8][4];                            // [phase][f,i,o,g_q]

    const unsigned m = 0xffffffffu;

    // SMEM exchange pointers
    float* slot[2] = { &hxch[0][wrp][lane],        &hxch[1][wrp][lane] };
    const float4* row[2] = {
        (const float4*)&hxch[0][wrp][lane & 24],   // my group's 8 h values
        (const float4*)&hxch[1][wrp][lane & 24]
    };

    auto FLAG_ADDR = [&](int tbase) -> const unsigned* {
        int tp = tbase + (lane & 7);
        if (tp > TT-1) tp = TT-1;
        return &g_ready[tp];
    };

    auto POLL_BLOCK = [&](int tbase){          // blocking (startup/slow path)
        const unsigned* fp = FLAG_ADDR(tbase);
        unsigned v;
        do { v = flag_acq(fp); } while (!__all_sync(m, v != 0));
    };

    auto LOAD = [&](float* p, int t){
        const float* base = pre + (long long)t*PSTR;
        p[0] = __ldg(base);                    // f pre-activation
        p[1] = __ldg(base + BB);               // i
        p[2] = __ldg(base + 2*BB);             // o
        p[3] = __ldg(base + (3 + q)*BB);       // my g row
    };

    auto STEP = [&](int t, const float* p){
        const int buf = t & 1;
        // h exchange through warp-private SMEM row
        *slot[buf] = h;                        // STS
        __syncwarp(m);
        const float4 Ha = row[buf][0];         // LDS.128 (broadcast in group)
        const float4 Hb = row[buf][1];
        const float H[8] = {Ha.x, Ha.y, Ha.z, Ha.w, Hb.x, Hb.y, Hb.z, Hb.w};

        // 4 local dots (f, i, o, my g), dual accumulators
        float zf = p[0], zi = p[1], zo = p[2], zg = p[3];
        float zfA = 0.f, ziA = 0.f, zoA = 0.f, zgA = 0.f;
#pragma unroll
        for (int r = 0; r < 8; r += 2){
            zf  = fmaf(wf8[r],   H[r],   zf );
            zfA = fmaf(wf8[r+1], H[r+1], zfA);
            zi  = fmaf(wi8[r],   H[r],   zi );
            ziA = fmaf(wi8[r+1], H[r+1], ziA);
            zo  = fmaf(wo8[r],   H[r],   zo );
            zoA = fmaf(wo8[r+1], H[r+1], zoA);
            zg  = fmaf(wu8[r],   H[r],   zg );
            zgA = fmaf(wu8[r+1], H[r+1], zgA);
        }
        zf += zfA; zi += ziA; zo += zoA; zg += zgA;

        const float f = sigm_poly(cgf * __cosf(zf));
        const float i = sigm_poly(cgi * __cosf(zi));
        const float o = sigm_poly(cgo * __cosf(zo));
        const float g = tanh_fast(zg);

        c = fmaf(f, c, i*g);
        h = o * tanh_fast(c);

        out[((long long)t*BB + b)*8 + q] = h;   // warp: 128B contiguous
    };

    // Startup: block on group 0, prime ring, prefetch flag for group 8.
    POLL_BLOCK(0);
#pragma unroll
    for (int ph = 0; ph < 8; ph++) LOAD(pr[ph], ph);
    unsigned fv = flag_acq(FLAG_ADDR(8));

    for (int tb = 0; tb < TT; tb += 8){
        if (!__all_sync(m, fv != 0))
            POLL_BLOCK(tb + 8);                 // rare slow path
        fv = flag_acq(FLAG_ADDR(tb + 16));      // prefetch next group's flags
#pragma unroll
        for (int ph = 0; ph < 8; ph++){
            STEP(tb + ph, pr[ph]);
            int tn = tb + ph + 8; if (tn >= TT) tn = TT - 1;
            LOAD(pr[ph], tn);
        }
    }

    if (write_tail){
        float* hp = out + (long long)TT*BB*8;
        hp[b*8 + q]         = h;
        hp[BB*8 + b*8 + q]  = c;
    }
}

// ---------------------------------------------------------------------------
extern "C" void kernel_launch(void* const* d_in, const int* in_sizes, int n_in,
                              void* d_out, int out_size)
{
    const float* x   = (const float*)d_in[0];
    const float* Wf  = (const float*)d_in[1];
    const float* bf  = (const float*)d_in[2];
    const float* Wi  = (const float*)d_in[3];
    const float* bi  = (const float*)d_in[4];
    const float* Wu  = (const float*)d_in[5];
    const float* bu  = (const float*)d_in[6];
    const float* Wo  = (const float*)d_in[7];
    const float* bo  = (const float*)d_in[8];
    const float* qwf = (const float*)d_in[9];
    const float* qwi = (const float*)d_in[10];
    // d_in[11] = qwu: unused — g path has no quantum gate in the reference
    const float* qwo = (const float*)d_in[12];
    float* out = (float*)d_out;

    const int write_tail = (out_size >= TT*BB*8 + 2*BB*8) ? 1 : 0;

    fused_kernel<<<PREPB + RECB, 128>>>(x, Wf, bf, Wi, bi, Wu, bu, Wo, bo,
                                        qwf, qwi, qwo, out, write_tail);
}